// round 3
// baseline (speedup 1.0000x reference)
#include <cuda_runtime.h>
#include <mma.h>
#include <math.h>
#include <stdint.h>

using namespace nvcuda;

#define BB   2
#define SS   8192
#define DD   1024
#define NWIN 7
#define NBW  14
#define WLEN 2048
#define GG   128

// ---------------- static scratch ----------------
__device__ float g_Sscr [(size_t)NBW * WLEN * WLEN];   // scores; reused as mw logits
__device__ float g_Oscr [(size_t)NBW * WLEN * DD];     // window outs; reused as mixed
__device__ float g_local[(size_t)BB * SS * DD];
__device__ float g_glob [(size_t)BB * SS * DD];
__device__ float g_xt   [(size_t)BB * DD * SS];
__device__ float g_bcast[(size_t)BB * SS * DD];
__device__ float g_gt   [(size_t)BB * 256 * DD];
__device__ float g_lg2  [(size_t)BB * SS * 256];
__device__ float g_Wc2  [(size_t)DD * 4096];

struct GP {
    const float* A;
    const float* A2;    // second A matrix for K-concat (nullptr if unused)
    const float* B;
    float* C;
    int lda, ldb, ldc;
    long sA, sB, sC;
    int K;
    int kSplit;         // K boundary between A and A2
    float alpha;
    int beta;
    int winA, winB;
    int causal;
    int klimit;
};

__device__ __forceinline__ long window_off(int z) {
    return (long)(z / NWIN) * ((long)SS * DD) + (long)(z % NWIN) * (1024L * DD);
}

__device__ __forceinline__ void cp16(void* smem, const void* g) {
    uint32_t s = (uint32_t)__cvta_generic_to_shared(smem);
    asm volatile("cp.async.ca.shared.global [%0], [%1], 16;\n" :: "r"(s), "l"(g));
}
__device__ __forceinline__ void cp_commit() { asm volatile("cp.async.commit_group;\n"); }
template<int N> __device__ __forceinline__ void cp_wait() { asm volatile("cp.async.wait_group %0;\n" :: "n"(N)); }

// TB=1: C = A*B^T ; TB=0: C = A*B   (A,B row-major). 4-stage cp.async pipeline.
template<int TB>
__global__ void __launch_bounds__(256) gemm_tf32(GP p) {
    constexpr int BM = 128, BN = 128, BK = 16, ST = 4;
    constexpr int AKP = 20;                    // A smem row stride (floats)
    constexpr int BLD = TB ? 20 : 132;         // B smem row stride
    constexpr int BROWS = TB ? 128 : 16;
    constexpr int ASTG = BM * AKP;             // floats per A stage
    constexpr int BSTG = BROWS * BLD;          // floats per B stage

    int i0 = blockIdx.y * BM;
    int j0 = blockIdx.x * BN;
    if (p.causal && j0 > i0) return;
    int z = blockIdx.z;
    const float* A  = p.A + (p.winA ? window_off(z) : z * p.sA);
    const float* Bm = p.B + (p.winB ? window_off(z) : z * p.sB);
    float* C = p.C + z * p.sC;
    int K  = p.klimit ? min(p.K, i0 + BM) : p.K;
    int KT = K / BK;

    extern __shared__ float smem_dyn[];
    float* Asm = smem_dyn;                 // [ST][BM][AKP]
    float* Bsm = smem_dyn + ST * ASTG;     // [ST][BROWS][BLD]

    int tid = threadIdx.x;
    int ar = tid >> 2, ac = (tid & 3) << 2;
    int br, bcd;
    if (TB) { br = tid >> 2;  bcd = (tid & 3) << 2;  }
    else    { br = tid >> 5;  bcd = (tid & 31) << 2; }

    auto load_tile = [&](int kt, int sl) {
        long acol = (long)kt * BK;
        const float* Ag;
        if (p.A2 && acol >= p.kSplit)
            Ag = p.A2 + (long)(i0 + ar) * p.lda + (acol - p.kSplit) + ac;
        else
            Ag = A + (long)(i0 + ar) * p.lda + acol + ac;
        float* As = Asm + sl * ASTG;
        cp16(&As[ar * AKP + ac],        Ag);
        cp16(&As[(ar + 64) * AKP + ac], Ag + (long)64 * p.lda);
        float* Bs = Bsm + sl * BSTG;
        if (TB) {
            const float* Bg = Bm + (long)(j0 + br) * p.ldb + acol + bcd;
            cp16(&Bs[br * BLD + bcd],        Bg);
            cp16(&Bs[(br + 64) * BLD + bcd], Bg + (long)64 * p.ldb);
        } else {
            const float* Bg = Bm + (acol + br) * (long)p.ldb + j0 + bcd;
            cp16(&Bs[br * BLD + bcd],       Bg);
            cp16(&Bs[(br + 8) * BLD + bcd], Bg + (long)8 * p.ldb);
        }
    };

    // prologue: ST-1 stages in flight
    #pragma unroll
    for (int s = 0; s < ST - 1; s++) {
        if (s < KT) load_tile(s, s);
        cp_commit();
    }

    int wid = tid >> 5;
    int wr  = (wid & 3) * 32;
    int wc  = (wid >> 2) * 64;

    wmma::fragment<wmma::accumulator, 16, 16, 8, float> acc[2][4];
    #pragma unroll
    for (int i = 0; i < 2; i++)
        #pragma unroll
        for (int j = 0; j < 4; j++) wmma::fill_fragment(acc[i][j], 0.0f);

    for (int kt = 0; kt < KT; kt++) {
        if (kt + ST - 1 < KT) load_tile(kt + ST - 1, (kt + ST - 1) & (ST - 1));
        cp_commit();
        cp_wait<ST - 2>();
        __syncthreads();

        int sl = kt & (ST - 1);
        const float* As = Asm + sl * ASTG;
        const float* Bs = Bsm + sl * BSTG;

        #pragma unroll
        for (int ks = 0; ks < 2; ks++) {
            wmma::fragment<wmma::matrix_a, 16, 16, 8, wmma::precision::tf32, wmma::row_major> af[2];
            #pragma unroll
            for (int i = 0; i < 2; i++) {
                wmma::load_matrix_sync(af[i], &As[(wr + i * 16) * AKP + ks * 8], AKP);
                #pragma unroll
                for (int t = 0; t < af[i].num_elements; t++)
                    af[i].x[t] = wmma::__float_to_tf32(af[i].x[t]);
            }
            #pragma unroll
            for (int j = 0; j < 4; j++) {
                if (TB) {
                    wmma::fragment<wmma::matrix_b, 16, 16, 8, wmma::precision::tf32, wmma::col_major> bf;
                    wmma::load_matrix_sync(bf, &Bs[(wc + j * 16) * BLD + ks * 8], BLD);
                    #pragma unroll
                    for (int t = 0; t < bf.num_elements; t++) bf.x[t] = wmma::__float_to_tf32(bf.x[t]);
                    wmma::mma_sync(acc[0][j], af[0], bf, acc[0][j]);
                    wmma::mma_sync(acc[1][j], af[1], bf, acc[1][j]);
                } else {
                    wmma::fragment<wmma::matrix_b, 16, 16, 8, wmma::precision::tf32, wmma::row_major> bf;
                    wmma::load_matrix_sync(bf, &Bs[(ks * 8) * BLD + wc + j * 16], BLD);
                    #pragma unroll
                    for (int t = 0; t < bf.num_elements; t++) bf.x[t] = wmma::__float_to_tf32(bf.x[t]);
                    wmma::mma_sync(acc[0][j], af[0], bf, acc[0][j]);
                    wmma::mma_sync(acc[1][j], af[1], bf, acc[1][j]);
                }
            }
        }
        __syncthreads();
    }

    #pragma unroll
    for (int i = 0; i < 2; i++)
        #pragma unroll
        for (int j = 0; j < 4; j++) {
            #pragma unroll
            for (int t = 0; t < acc[i][j].num_elements; t++) acc[i][j].x[t] *= p.alpha;
            float* cp = C + (long)(i0 + wr + i * 16) * p.ldc + j0 + wc + j * 16;
            if (p.beta) {
                wmma::fragment<wmma::accumulator, 16, 16, 8, float> cf;
                wmma::load_matrix_sync(cf, cp, p.ldc, wmma::mem_row_major);
                #pragma unroll
                for (int t = 0; t < acc[i][j].num_elements; t++) acc[i][j].x[t] += cf.x[t];
            }
            wmma::store_matrix_sync(cp, acc[i][j], p.ldc, wmma::mem_row_major);
        }
}

// smem sizes (bytes) for the two instantiations
#define SMEM_TB1 ((4 * (128 * 20) + 4 * (128 * 20)) * 4)
#define SMEM_TB0 ((4 * (128 * 20) + 4 * (16 * 132)) * 4)

// ---------------- transpose (z, R x C) -> (z, C x R) ----------------
__global__ void transpose_k(const float* __restrict__ in, float* __restrict__ out, int R, int C) {
    __shared__ float t[32][33];
    long bo = (long)blockIdx.z * R * C;
    int r0 = blockIdx.y * 32, c0 = blockIdx.x * 32;
    int tx = threadIdx.x, ty = threadIdx.y;
    #pragma unroll
    for (int k = 0; k < 32; k += 8)
        t[ty + k][tx] = in[bo + (long)(r0 + ty + k) * C + c0 + tx];
    __syncthreads();
    #pragma unroll
    for (int k = 0; k < 32; k += 8)
        out[bo + (long)(c0 + ty + k) * R + r0 + tx] = t[tx][ty + k];
}

// ---------------- broadcast: per-(b,d) channel, in place on g_xt ----------------
__global__ void __launch_bounds__(256) bcast_k(float* xt) {
    __shared__ float a[SS];
    float res[32], nv[32];
    float* g = xt + (long)blockIdx.x * SS;
    int tid = threadIdx.x;
    #pragma unroll
    for (int j = 0; j < 32; j++) { a[tid + 256 * j] = g[tid + 256 * j]; res[j] = 0.0f; }
    __syncthreads();
    for (int s = 1; s < SS; s <<= 1) {
        #pragma unroll
        for (int j = 0; j < 32; j++) {
            int i = tid + 256 * j;
            nv[j] = a[i] + 0.5f * (a[(i - s) & (SS - 1)] + a[(i + s) & (SS - 1)]);
        }
        __syncthreads();
        #pragma unroll
        for (int j = 0; j < 32; j++) { int i = tid + 256 * j; a[i] = nv[j]; res[j] += nv[j]; }
        __syncthreads();
    }
    const float inv = 1.0f / 14.0f;
    #pragma unroll
    for (int j = 0; j < 32; j++) g[tid + 256 * j] = res[j] * inv;
}

// ---------------- Wc (o,d,k) -> Wc2 (o, k*1024+d) ----------------
__global__ void wc_reorder(const float* __restrict__ Wc, float* __restrict__ Wc2) {
    long idx = (long)blockIdx.x * 256 + threadIdx.x;
    int o = (int)(idx >> 12);
    int rem = (int)(idx & 4095);
    int k = rem >> 10;
    int d = rem & 1023;
    Wc2[idx] = Wc[(long)o * 4096 + d * 4 + k];
}

// ---------------- gt init: rows<128 = bc (bias preload), rows>=128 = gm ----------------
__global__ void build_gt(const float* __restrict__ gm, const float* __restrict__ bc, float* __restrict__ gt) {
    long idx = (long)blockIdx.x * 256 + threadIdx.x;
    int d = (int)(idx & 1023);
    int row = (int)((idx >> 10) & 255);
    gt[idx] = (row < GG) ? bc[d] : gm[(long)(row - GG) * DD + d];
}

__device__ __forceinline__ float blk_max(float v, float* red) {
    int tid = threadIdx.x;
    #pragma unroll
    for (int o = 16; o; o >>= 1) v = fmaxf(v, __shfl_xor_sync(0xffffffffu, v, o));
    if ((tid & 31) == 0) red[tid >> 5] = v;
    __syncthreads();
    float m = red[0];
    #pragma unroll
    for (int i = 1; i < 8; i++) m = fmaxf(m, red[i]);
    return m;
}
__device__ __forceinline__ float blk_sum(float v, float* red) {
    int tid = threadIdx.x;
    #pragma unroll
    for (int o = 16; o; o >>= 1) v += __shfl_xor_sync(0xffffffffu, v, o);
    if ((tid & 31) == 0) red[tid >> 5] = v;
    __syncthreads();
    float s = 0.f;
    #pragma unroll
    for (int i = 0; i < 8; i++) s += red[i];
    return s;
}

__global__ void softmax256(float* __restrict__ L) {
    __shared__ float red[8];
    float* r = L + (long)blockIdx.x * 256;
    int tid = threadIdx.x;
    float v = r[tid];
    float m = blk_max(v, red);
    __syncthreads();
    float e = expf(v - m);
    float s = blk_sum(e, red);
    r[tid] = e / s;
}

__global__ void softmax_causal(float* __restrict__ Sc) {
    __shared__ float red[8];
    int q = blockIdx.x, w = blockIdx.y;
    float* r = Sc + ((long)w * WLEN + q) * WLEN;
    int len = q + 1;
    int rb = ((q >> 7) + 1) << 7;
    int tid = threadIdx.x;
    float v[8];
    int cnt = 0;
    float m = -1e30f;
    for (int i = tid; i < len; i += 256) { v[cnt] = r[i]; m = fmaxf(m, v[cnt]); cnt++; }
    m = blk_max(m, red);
    __syncthreads();
    float s = 0.f;
    #pragma unroll
    for (int j = 0; j < 8; j++) if (j < cnt) { v[j] = expf(v[j] - m); s += v[j]; }
    s = blk_sum(s, red);
    float inv = 1.0f / s;
    cnt = 0;
    for (int i = tid; i < len; i += 256) r[i] = v[cnt++] * inv;
    for (int i = len + tid; i < rb; i += 256) r[i] = 0.0f;
}

__global__ void combine_local(const float* __restrict__ Oscr, float* __restrict__ local) {
    long idx = (long)blockIdx.x * 256 + threadIdx.x;
    int d = (int)(idx & 1023);
    long pd = idx >> 10;
    int p = (int)(pd & (SS - 1));
    int b = (int)(pd >> 13);
    int nhi = p >> 10;
    int n1 = min(nhi, NWIN - 1);
    int n0 = max(nhi - 1, 0);
    float acc = 0.f, wsum = 0.f;
    for (int n = n0; n <= n1; n++) {
        int q = p - (n << 10);
        float tri = 0.5f + q * (1.0f / 2047.0f);
        acc  += Oscr[(((long)(b * NWIN + n)) * WLEN + q) * DD + d] * tri;
        wsum += tri;
    }
    local[idx] = acc / (wsum + 1e-6f);
}

__global__ void sigmoid_mix(const float* __restrict__ mwl, const float* __restrict__ bm,
                            const float* __restrict__ local, const float* __restrict__ glob,
                            const float* __restrict__ bcast, float* __restrict__ mixed) {
    long idx = (long)blockIdx.x * 256 + threadIdx.x;
    int o = (int)(idx & 1023);
    float g = 1.0f / (1.0f + expf(-(mwl[idx] + bm[o])));
    mixed[idx] = g * local[idx] + (1.0f - g) * glob[idx] + bcast[idx];
}

__global__ void fill_bias(float* __restrict__ out, const float* __restrict__ bo) {
    long idx = (long)blockIdx.x * 256 + threadIdx.x;
    out[idx] = bo[idx & 1023];
}

extern "C" void kernel_launch(void* const* d_in, const int* in_sizes, int n_in,
                              void* d_out, int out_size) {
    const float* x  = (const float*)d_in[0];
    const float* gm = (const float*)d_in[1];
    const float* Wc = (const float*)d_in[2];
    const float* bc = (const float*)d_in[3];
    const float* Wm = (const float*)d_in[4];
    const float* bm = (const float*)d_in[5];
    const float* Wo = (const float*)d_in[6];
    const float* bo = (const float*)d_in[7];
    float* out = (float*)d_out;

    float *Sscr, *Oscr, *local, *glob, *xt, *bcast, *gt, *lg2, *Wc2;
    cudaGetSymbolAddress((void**)&Sscr,  g_Sscr);
    cudaGetSymbolAddress((void**)&Oscr,  g_Oscr);
    cudaGetSymbolAddress((void**)&local, g_local);
    cudaGetSymbolAddress((void**)&glob,  g_glob);
    cudaGetSymbolAddress((void**)&xt,    g_xt);
    cudaGetSymbolAddress((void**)&bcast, g_bcast);
    cudaGetSymbolAddress((void**)&gt,    g_gt);
    cudaGetSymbolAddress((void**)&lg2,   g_lg2);
    cudaGetSymbolAddress((void**)&Wc2,   g_Wc2);

    cudaFuncSetAttribute(gemm_tf32<1>, cudaFuncAttributeMaxDynamicSharedMemorySize, SMEM_TB1);
    cudaFuncSetAttribute(gemm_tf32<0>, cudaFuncAttributeMaxDynamicSharedMemorySize, SMEM_TB0);

    const float isq = 1.0f / 32.0f;
    const long SD = (long)SS * DD;

    wc_reorder<<<16384, 256>>>(Wc, Wc2);
    build_gt<<<2048, 256>>>(gm, bc, gt);

    // comp = x(b,128rows,4096) @ Wc2^T (+bc preloaded in gt rows 0..127)
    {
        GP p{}; p.A = x; p.A2 = nullptr; p.B = Wc2; p.C = gt;
        p.lda = 4096; p.ldb = 4096; p.ldc = 1024;
        p.sA = SD; p.sB = 0; p.sC = 256L * 1024;
        p.K = 4096; p.kSplit = 0; p.alpha = 1.0f; p.beta = 1;
        p.winA = 0; p.winB = 0; p.causal = 0; p.klimit = 0;
        gemm_tf32<1><<<dim3(8, 1, 2), 256, SMEM_TB1>>>(p);
    }
    // logits = x @ gt^T / 32
    {
        GP p{}; p.A = x; p.A2 = nullptr; p.B = gt; p.C = lg2;
        p.lda = 1024; p.ldb = 1024; p.ldc = 256;
        p.sA = SD; p.sB = 256L * 1024; p.sC = (long)SS * 256;
        p.K = 1024; p.kSplit = 0; p.alpha = isq; p.beta = 0;
        p.winA = 0; p.winB = 0; p.causal = 0; p.klimit = 0;
        gemm_tf32<1><<<dim3(2, 64, 2), 256, SMEM_TB1>>>(p);
    }
    softmax256<<<BB * SS, 256>>>(lg2);
    // glob = attn @ gt
    {
        GP p{}; p.A = lg2; p.A2 = nullptr; p.B = gt; p.C = glob;
        p.lda = 256; p.ldb = 1024; p.ldc = 1024;
        p.sA = (long)SS * 256; p.sB = 256L * 1024; p.sC = SD;
        p.K = 256; p.kSplit = 0; p.alpha = 1.0f; p.beta = 0;
        p.winA = 0; p.winB = 0; p.causal = 0; p.klimit = 0;
        gemm_tf32<0><<<dim3(8, 64, 2), 256, SMEM_TB0>>>(p);
    }
    // window scores = w @ w^T / 32 (causal tile-skip)
    {
        GP p{}; p.A = x; p.A2 = nullptr; p.B = x; p.C = Sscr;
        p.lda = 1024; p.ldb = 1024; p.ldc = WLEN;
        p.sA = 0; p.sB = 0; p.sC = (long)WLEN * WLEN;
        p.K = 1024; p.kSplit = 0; p.alpha = isq; p.beta = 0;
        p.winA = 1; p.winB = 1; p.causal = 1; p.klimit = 0;
        gemm_tf32<1><<<dim3(16, 16, NBW), 256, SMEM_TB1>>>(p);
    }
    softmax_causal<<<dim3(WLEN, NBW), 256>>>(Sscr);
    // out_w = P @ w (K limited per row block)
    {
        GP p{}; p.A = Sscr; p.A2 = nullptr; p.B = x; p.C = Oscr;
        p.lda = WLEN; p.ldb = 1024; p.ldc = 1024;
        p.sA = (long)WLEN * WLEN; p.sB = 0; p.sC = (long)WLEN * DD;
        p.K = WLEN; p.kSplit = 0; p.alpha = 1.0f; p.beta = 0;
        p.winA = 0; p.winB = 1; p.causal = 0; p.klimit = 1;
        gemm_tf32<0><<<dim3(8, 16, NBW), 256, SMEM_TB0>>>(p);
    }
    combine_local<<<65536, 256>>>(Oscr, local);

    // broadcast path
    transpose_k<<<dim3(32, 256, 2), dim3(32, 8)>>>(x, xt, SS, DD);
    bcast_k<<<BB * DD, 256>>>(xt);
    transpose_k<<<dim3(256, 32, 2), dim3(32, 8)>>>(xt, bcast, DD, SS);

    // mw logits = [local|glob] @ Wm^T  (fused dual-A, K=2048)
    {
        GP p{}; p.A = local; p.A2 = glob; p.B = Wm; p.C = Sscr;
        p.lda = 1024; p.ldb = 2048; p.ldc = 1024;
        p.sA = 0; p.sB = 0; p.sC = 0;
        p.K = 2048; p.kSplit = 1024; p.alpha = 1.0f; p.beta = 0;
        p.winA = 0; p.winB = 0; p.causal = 0; p.klimit = 0;
        gemm_tf32<1><<<dim3(8, 128, 1), 256, SMEM_TB1>>>(p);
    }
    sigmoid_mix<<<65536, 256>>>(Sscr, bm, local, glob, bcast, Oscr);

    // out = mixed @ Wo^T + bo
    fill_bias<<<65536, 256>>>(out, bo);
    {
        GP p{}; p.A = Oscr; p.A2 = nullptr; p.B = Wo; p.C = out;
        p.lda = 1024; p.ldb = 1024; p.ldc = 1024;
        p.sA = 0; p.sB = 0; p.sC = 0;
        p.K = 1024; p.kSplit = 0; p.alpha = 1.0f; p.beta = 1;
        p.winA = 0; p.winB = 0; p.causal = 0; p.klimit = 0;
        gemm_tf32<1><<<dim3(8, 128, 1), 256, SMEM_TB1>>>(p);
    }
}

// round 4
// speedup vs baseline: 1.0342x; 1.0342x over previous
#include <cuda_runtime.h>
#include <mma.h>
#include <math.h>
#include <stdint.h>

using namespace nvcuda;

#define BB   2
#define SS   8192
#define DD   1024
#define NWIN 7
#define NBW  14
#define WLEN 2048
#define GG   128

// ---------------- static scratch ----------------
__device__ float g_Sscr [(size_t)NBW * WLEN * WLEN];   // scores; reused as mw logits
__device__ float g_Oscr [(size_t)NBW * WLEN * DD];     // window outs; reused as mixed
__device__ float g_local[(size_t)BB * SS * DD];
__device__ float g_glob [(size_t)BB * SS * DD];
__device__ float g_xt   [(size_t)BB * DD * SS];
__device__ float g_bcast[(size_t)BB * SS * DD];
__device__ float g_gt   [(size_t)BB * 256 * DD];
__device__ float g_lg2  [(size_t)BB * SS * 256];
__device__ float g_Wc2  [(size_t)DD * 4096];
__device__ float g_xr   [(size_t)BB * SS * DD];        // tf32-rounded x
__device__ float g_Wmr  [(size_t)DD * 2 * DD];
__device__ float g_Wor  [(size_t)DD * DD];

__device__ __forceinline__ float rtf32(float v) {
    unsigned u;
    asm("cvt.rna.tf32.f32 %0, %1;" : "=r"(u) : "f"(v));
    return __uint_as_float(u);
}

struct GP {
    const float* A;
    const float* A2;    // second A matrix for K-concat (nullptr if unused)
    const float* B;
    float* C;
    int lda, ldb, ldc;
    long sA, sB, sC;
    int K;
    int kSplit;
    float alpha;
    int beta;
    int winA, winB;
    int causal;
    int klimit;
    int roundOut;       // round C to tf32 before store
};

__device__ __forceinline__ long window_off(int z) {
    return (long)(z / NWIN) * ((long)SS * DD) + (long)(z % NWIN) * (1024L * DD);
}

__device__ __forceinline__ void cp16(void* smem, const void* g) {
    uint32_t s = (uint32_t)__cvta_generic_to_shared(smem);
    asm volatile("cp.async.ca.shared.global [%0], [%1], 16;\n" :: "r"(s), "l"(g));
}
__device__ __forceinline__ void cp_commit() { asm volatile("cp.async.commit_group;\n"); }
template<int N> __device__ __forceinline__ void cp_wait() { asm volatile("cp.async.wait_group %0;\n" :: "n"(N)); }

// TB=1: C = A*B^T ; TB=0: C = A*B. Operands MUST be pre-rounded to tf32.
template<int TB>
__global__ void __launch_bounds__(256) gemm_tf32(GP p) {
    constexpr int BM = 128, BN = 128, BK = 16, ST = 4;
    constexpr int AKP = 20;
    constexpr int BLD = TB ? 20 : 132;
    constexpr int BROWS = TB ? 128 : 16;
    constexpr int ASTG = BM * AKP;
    constexpr int BSTG = BROWS * BLD;

    int i0 = blockIdx.y * BM;
    int j0 = blockIdx.x * BN;
    if (p.causal && j0 > i0) return;
    int z = blockIdx.z;
    const float* A  = p.A + (p.winA ? window_off(z) : z * p.sA);
    const float* Bm = p.B + (p.winB ? window_off(z) : z * p.sB);
    float* C = p.C + z * p.sC;
    int K  = p.klimit ? min(p.K, i0 + BM) : p.K;
    int KT = K / BK;

    extern __shared__ float smem_dyn[];
    float* Asm = smem_dyn;
    float* Bsm = smem_dyn + ST * ASTG;

    int tid = threadIdx.x;
    int ar = tid >> 2, ac = (tid & 3) << 2;
    int br, bcd;
    if (TB) { br = tid >> 2;  bcd = (tid & 3) << 2;  }
    else    { br = tid >> 5;  bcd = (tid & 31) << 2; }

    auto load_tile = [&](int kt, int sl) {
        long acol = (long)kt * BK;
        const float* Ag;
        if (p.A2 && acol >= p.kSplit)
            Ag = p.A2 + (long)(i0 + ar) * p.lda + (acol - p.kSplit) + ac;
        else
            Ag = A + (long)(i0 + ar) * p.lda + acol + ac;
        float* As = Asm + sl * ASTG;
        cp16(&As[ar * AKP + ac],        Ag);
        cp16(&As[(ar + 64) * AKP + ac], Ag + (long)64 * p.lda);
        float* Bs = Bsm + sl * BSTG;
        if (TB) {
            const float* Bg = Bm + (long)(j0 + br) * p.ldb + acol + bcd;
            cp16(&Bs[br * BLD + bcd],        Bg);
            cp16(&Bs[(br + 64) * BLD + bcd], Bg + (long)64 * p.ldb);
        } else {
            const float* Bg = Bm + (acol + br) * (long)p.ldb + j0 + bcd;
            cp16(&Bs[br * BLD + bcd],       Bg);
            cp16(&Bs[(br + 8) * BLD + bcd], Bg + (long)8 * p.ldb);
        }
    };

    #pragma unroll
    for (int s = 0; s < ST - 1; s++) {
        if (s < KT) load_tile(s, s);
        cp_commit();
    }

    int wid = tid >> 5;
    int wr  = (wid & 3) * 32;
    int wc  = (wid >> 2) * 64;

    wmma::fragment<wmma::accumulator, 16, 16, 8, float> acc[2][4];
    #pragma unroll
    for (int i = 0; i < 2; i++)
        #pragma unroll
        for (int j = 0; j < 4; j++) wmma::fill_fragment(acc[i][j], 0.0f);

    for (int kt = 0; kt < KT; kt++) {
        cp_wait<ST - 2>();
        __syncthreads();
        if (kt + ST - 1 < KT) load_tile(kt + ST - 1, (kt + ST - 1) & (ST - 1));
        cp_commit();

        int sl = kt & (ST - 1);
        const float* As = Asm + sl * ASTG;
        const float* Bs = Bsm + sl * BSTG;

        #pragma unroll
        for (int ks = 0; ks < 2; ks++) {
            wmma::fragment<wmma::matrix_a, 16, 16, 8, wmma::precision::tf32, wmma::row_major> af[2];
            #pragma unroll
            for (int i = 0; i < 2; i++)
                wmma::load_matrix_sync(af[i], &As[(wr + i * 16) * AKP + ks * 8], AKP);
            #pragma unroll
            for (int j = 0; j < 4; j++) {
                if (TB) {
                    wmma::fragment<wmma::matrix_b, 16, 16, 8, wmma::precision::tf32, wmma::col_major> bf;
                    wmma::load_matrix_sync(bf, &Bs[(wc + j * 16) * BLD + ks * 8], BLD);
                    wmma::mma_sync(acc[0][j], af[0], bf, acc[0][j]);
                    wmma::mma_sync(acc[1][j], af[1], bf, acc[1][j]);
                } else {
                    wmma::fragment<wmma::matrix_b, 16, 16, 8, wmma::precision::tf32, wmma::row_major> bf;
                    wmma::load_matrix_sync(bf, &Bs[(ks * 8) * BLD + wc + j * 16], BLD);
                    wmma::mma_sync(acc[0][j], af[0], bf, acc[0][j]);
                    wmma::mma_sync(acc[1][j], af[1], bf, acc[1][j]);
                }
            }
        }
    }

    #pragma unroll
    for (int i = 0; i < 2; i++)
        #pragma unroll
        for (int j = 0; j < 4; j++) {
            #pragma unroll
            for (int t = 0; t < acc[i][j].num_elements; t++) acc[i][j].x[t] *= p.alpha;
            float* cp = C + (long)(i0 + wr + i * 16) * p.ldc + j0 + wc + j * 16;
            if (p.beta) {
                wmma::fragment<wmma::accumulator, 16, 16, 8, float> cf;
                wmma::load_matrix_sync(cf, cp, p.ldc, wmma::mem_row_major);
                #pragma unroll
                for (int t = 0; t < acc[i][j].num_elements; t++) acc[i][j].x[t] += cf.x[t];
            }
            if (p.roundOut) {
                #pragma unroll
                for (int t = 0; t < acc[i][j].num_elements; t++) acc[i][j].x[t] = rtf32(acc[i][j].x[t]);
            }
            wmma::store_matrix_sync(cp, acc[i][j], p.ldc, wmma::mem_row_major);
        }
}

#define SMEM_TB1 ((4 * (128 * 20) + 4 * (128 * 20)) * 4)
#define SMEM_TB0 ((4 * (128 * 20) + 4 * (16 * 132)) * 4)

// ---------------- rounded copy ----------------
__global__ void round_copy(const float* __restrict__ in, float* __restrict__ out, long n) {
    long idx = (long)blockIdx.x * 256 + threadIdx.x;
    if (idx < n) out[idx] = rtf32(in[idx]);
}

// ---------------- transpose (z, R x C) -> (z, C x R) ----------------
__global__ void transpose_k(const float* __restrict__ in, float* __restrict__ out, int R, int C) {
    __shared__ float t[32][33];
    long bo = (long)blockIdx.z * R * C;
    int r0 = blockIdx.y * 32, c0 = blockIdx.x * 32;
    int tx = threadIdx.x, ty = threadIdx.y;
    #pragma unroll
    for (int k = 0; k < 32; k += 8)
        t[ty + k][tx] = in[bo + (long)(r0 + ty + k) * C + c0 + tx];
    __syncthreads();
    #pragma unroll
    for (int k = 0; k < 32; k += 8)
        out[bo + (long)(c0 + ty + k) * R + r0 + tx] = t[tx][ty + k];
}

// ---------------- broadcast ----------------
__global__ void __launch_bounds__(256) bcast_k(float* xt) {
    __shared__ float a[SS];
    float res[32], nv[32];
    float* g = xt + (long)blockIdx.x * SS;
    int tid = threadIdx.x;
    #pragma unroll
    for (int j = 0; j < 32; j++) { a[tid + 256 * j] = g[tid + 256 * j]; res[j] = 0.0f; }
    __syncthreads();
    for (int s = 1; s < SS; s <<= 1) {
        #pragma unroll
        for (int j = 0; j < 32; j++) {
            int i = tid + 256 * j;
            nv[j] = a[i] + 0.5f * (a[(i - s) & (SS - 1)] + a[(i + s) & (SS - 1)]);
        }
        __syncthreads();
        #pragma unroll
        for (int j = 0; j < 32; j++) { int i = tid + 256 * j; a[i] = nv[j]; res[j] += nv[j]; }
        __syncthreads();
    }
    const float inv = 1.0f / 14.0f;
    #pragma unroll
    for (int j = 0; j < 32; j++) g[tid + 256 * j] = res[j] * inv;
}

__global__ void wc_reorder(const float* __restrict__ Wc, float* __restrict__ Wc2) {
    long idx = (long)blockIdx.x * 256 + threadIdx.x;
    int o = (int)(idx >> 12);
    int rem = (int)(idx & 4095);
    int k = rem >> 10;
    int d = rem & 1023;
    Wc2[idx] = rtf32(Wc[(long)o * 4096 + d * 4 + k]);
}

__global__ void build_gt(const float* __restrict__ gm, const float* __restrict__ bc, float* __restrict__ gt) {
    long idx = (long)blockIdx.x * 256 + threadIdx.x;
    int d = (int)(idx & 1023);
    int row = (int)((idx >> 10) & 255);
    gt[idx] = (row < GG) ? bc[d] : rtf32(gm[(long)(row - GG) * DD + d]);
}

__device__ __forceinline__ float blk_max(float v, float* red) {
    int tid = threadIdx.x;
    #pragma unroll
    for (int o = 16; o; o >>= 1) v = fmaxf(v, __shfl_xor_sync(0xffffffffu, v, o));
    if ((tid & 31) == 0) red[tid >> 5] = v;
    __syncthreads();
    float m = red[0];
    #pragma unroll
    for (int i = 1; i < 8; i++) m = fmaxf(m, red[i]);
    return m;
}
__device__ __forceinline__ float blk_sum(float v, float* red) {
    int tid = threadIdx.x;
    #pragma unroll
    for (int o = 16; o; o >>= 1) v += __shfl_xor_sync(0xffffffffu, v, o);
    if ((tid & 31) == 0) red[tid >> 5] = v;
    __syncthreads();
    float s = 0.f;
    #pragma unroll
    for (int i = 0; i < 8; i++) s += red[i];
    return s;
}

__global__ void softmax256(float* __restrict__ L) {
    __shared__ float red[8];
    float* r = L + (long)blockIdx.x * 256;
    int tid = threadIdx.x;
    float v = r[tid];
    float m = blk_max(v, red);
    __syncthreads();
    float e = expf(v - m);
    float s = blk_sum(e, red);
    r[tid] = rtf32(e / s);
}

__global__ void softmax_causal(float* __restrict__ Sc) {
    __shared__ float red[8];
    int q = blockIdx.x, w = blockIdx.y;
    float* r = Sc + ((long)w * WLEN + q) * WLEN;
    int len = q + 1;
    int rb = ((q >> 7) + 1) << 7;
    int tid = threadIdx.x;
    float v[8];
    int cnt = 0;
    float m = -1e30f;
    for (int i = tid; i < len; i += 256) { v[cnt] = r[i]; m = fmaxf(m, v[cnt]); cnt++; }
    m = blk_max(m, red);
    __syncthreads();
    float s = 0.f;
    #pragma unroll
    for (int j = 0; j < 8; j++) if (j < cnt) { v[j] = expf(v[j] - m); s += v[j]; }
    s = blk_sum(s, red);
    float inv = 1.0f / s;
    cnt = 0;
    for (int i = tid; i < len; i += 256) r[i] = rtf32(v[cnt++] * inv);
    for (int i = len + tid; i < rb; i += 256) r[i] = 0.0f;
}

__global__ void combine_local(const float* __restrict__ Oscr, float* __restrict__ local) {
    long idx = (long)blockIdx.x * 256 + threadIdx.x;
    int d = (int)(idx & 1023);
    long pd = idx >> 10;
    int p = (int)(pd & (SS - 1));
    int b = (int)(pd >> 13);
    int nhi = p >> 10;
    int n1 = min(nhi, NWIN - 1);
    int n0 = max(nhi - 1, 0);
    float acc = 0.f, wsum = 0.f;
    for (int n = n0; n <= n1; n++) {
        int q = p - (n << 10);
        float tri = 0.5f + q * (1.0f / 2047.0f);
        acc  += Oscr[(((long)(b * NWIN + n)) * WLEN + q) * DD + d] * tri;
        wsum += tri;
    }
    local[idx] = rtf32(acc / (wsum + 1e-6f));
}

__global__ void sigmoid_mix(const float* __restrict__ mwl, const float* __restrict__ bm,
                            const float* __restrict__ local, const float* __restrict__ glob,
                            const float* __restrict__ bcast, float* __restrict__ mixed) {
    long idx = (long)blockIdx.x * 256 + threadIdx.x;
    int o = (int)(idx & 1023);
    float g = 1.0f / (1.0f + expf(-(mwl[idx] + bm[o])));
    mixed[idx] = rtf32(g * local[idx] + (1.0f - g) * glob[idx] + bcast[idx]);
}

__global__ void fill_bias(float* __restrict__ out, const float* __restrict__ bo) {
    long idx = (long)blockIdx.x * 256 + threadIdx.x;
    out[idx] = bo[idx & 1023];
}

extern "C" void kernel_launch(void* const* d_in, const int* in_sizes, int n_in,
                              void* d_out, int out_size) {
    const float* x  = (const float*)d_in[0];
    const float* gm = (const float*)d_in[1];
    const float* Wc = (const float*)d_in[2];
    const float* bc = (const float*)d_in[3];
    const float* Wm = (const float*)d_in[4];
    const float* bm = (const float*)d_in[5];
    const float* Wo = (const float*)d_in[6];
    const float* bo = (const float*)d_in[7];
    float* out = (float*)d_out;

    float *Sscr, *Oscr, *local, *glob, *xt, *bcast, *gt, *lg2, *Wc2, *xr, *Wmr, *Wor;
    cudaGetSymbolAddress((void**)&Sscr,  g_Sscr);
    cudaGetSymbolAddress((void**)&Oscr,  g_Oscr);
    cudaGetSymbolAddress((void**)&local, g_local);
    cudaGetSymbolAddress((void**)&glob,  g_glob);
    cudaGetSymbolAddress((void**)&xt,    g_xt);
    cudaGetSymbolAddress((void**)&bcast, g_bcast);
    cudaGetSymbolAddress((void**)&gt,    g_gt);
    cudaGetSymbolAddress((void**)&lg2,   g_lg2);
    cudaGetSymbolAddress((void**)&Wc2,   g_Wc2);
    cudaGetSymbolAddress((void**)&xr,    g_xr);
    cudaGetSymbolAddress((void**)&Wmr,   g_Wmr);
    cudaGetSymbolAddress((void**)&Wor,   g_Wor);

    cudaFuncSetAttribute(gemm_tf32<1>, cudaFuncAttributeMaxDynamicSharedMemorySize, SMEM_TB1);
    cudaFuncSetAttribute(gemm_tf32<0>, cudaFuncAttributeMaxDynamicSharedMemorySize, SMEM_TB0);

    const float isq = 1.0f / 32.0f;
    const long SD = (long)SS * DD;

    round_copy<<<(int)((SD * BB + 255) / 256), 256>>>(x, xr, SD * BB);
    round_copy<<<(2 * 1024 * 1024 + 255) / 256, 256>>>(Wm, Wmr, 2L * 1024 * 1024);
    round_copy<<<(1024 * 1024 + 255) / 256, 256>>>(Wo, Wor, 1024L * 1024);
    wc_reorder<<<16384, 256>>>(Wc, Wc2);
    build_gt<<<2048, 256>>>(gm, bc, gt);

    // comp = xr_view @ Wc2^T (+bc preload), rounded output
    {
        GP p{}; p.A = xr; p.B = Wc2; p.C = gt;
        p.lda = 4096; p.ldb = 4096; p.ldc = 1024;
        p.sA = SD; p.sC = 256L * 1024;
        p.K = 4096; p.alpha = 1.0f; p.beta = 1; p.roundOut = 1;
        gemm_tf32<1><<<dim3(8, 1, 2), 256, SMEM_TB1>>>(p);
    }
    // logits = xr @ gt^T / 32
    {
        GP p{}; p.A = xr; p.B = gt; p.C = lg2;
        p.lda = 1024; p.ldb = 1024; p.ldc = 256;
        p.sA = SD; p.sB = 256L * 1024; p.sC = (long)SS * 256;
        p.K = 1024; p.alpha = isq;
        gemm_tf32<1><<<dim3(2, 64, 2), 256, SMEM_TB1>>>(p);
    }
    softmax256<<<BB * SS, 256>>>(lg2);
    // glob = attn @ gt, rounded output
    {
        GP p{}; p.A = lg2; p.B = gt; p.C = glob;
        p.lda = 256; p.ldb = 1024; p.ldc = 1024;
        p.sA = (long)SS * 256; p.sB = 256L * 1024; p.sC = SD;
        p.K = 256; p.alpha = 1.0f; p.roundOut = 1;
        gemm_tf32<0><<<dim3(8, 64, 2), 256, SMEM_TB0>>>(p);
    }
    // window scores = w @ w^T / 32 (causal skip)
    {
        GP p{}; p.A = xr; p.B = xr; p.C = Sscr;
        p.lda = 1024; p.ldb = 1024; p.ldc = WLEN;
        p.sC = (long)WLEN * WLEN;
        p.K = 1024; p.alpha = isq;
        p.winA = 1; p.winB = 1; p.causal = 1;
        gemm_tf32<1><<<dim3(16, 16, NBW), 256, SMEM_TB1>>>(p);
    }
    softmax_causal<<<dim3(WLEN, NBW), 256>>>(Sscr);
    // out_w = P @ w (K limited per row block)
    {
        GP p{}; p.A = Sscr; p.B = xr; p.C = Oscr;
        p.lda = WLEN; p.ldb = 1024; p.ldc = 1024;
        p.sA = (long)WLEN * WLEN; p.sC = (long)WLEN * DD;
        p.K = WLEN; p.alpha = 1.0f;
        p.winB = 1; p.klimit = 1;
        gemm_tf32<0><<<dim3(8, 16, NBW), 256, SMEM_TB0>>>(p);
    }
    combine_local<<<65536, 256>>>(Oscr, local);

    // broadcast path
    transpose_k<<<dim3(32, 256, 2), dim3(32, 8)>>>(x, xt, SS, DD);
    bcast_k<<<BB * DD, 256>>>(xt);
    transpose_k<<<dim3(256, 32, 2), dim3(32, 8)>>>(xt, bcast, DD, SS);

    // mw logits = [local|glob] @ Wmr^T (fused dual-A, K=2048)
    {
        GP p{}; p.A = local; p.A2 = glob; p.B = Wmr; p.C = Sscr;
        p.lda = 1024; p.ldb = 2048; p.ldc = 1024;
        p.K = 2048; p.kSplit = 1024; p.alpha = 1.0f;
        gemm_tf32<1><<<dim3(8, 128, 1), 256, SMEM_TB1>>>(p);
    }
    sigmoid_mix<<<65536, 256>>>(Sscr, bm, local, glob, bcast, Oscr);

    // out = mixed @ Wor^T + bo
    fill_bias<<<65536, 256>>>(out, bo);
    {
        GP p{}; p.A = Oscr; p.B = Wor; p.C = out;
        p.lda = 1024; p.ldb = 1024; p.ldc = 1024;
        p.K = 1024; p.alpha = 1.0f; p.beta = 1;
        gemm_tf32<1><<<dim3(8, 128, 1), 256, SMEM_TB1>>>(p);
    }
}

// round 6
// speedup vs baseline: 1.0984x; 1.0620x over previous
#include <cuda_runtime.h>
#include <mma.h>
#include <math.h>
#include <stdint.h>

using namespace nvcuda;

#define BB   2
#define SS   8192
#define DD   1024
#define NWIN 7
#define NBW  14
#define WLEN 2048
#define GG   128

// ---------------- static scratch ----------------
__device__ float g_Sscr [(size_t)NBW * WLEN * WLEN];   // scores; reused as mw logits
__device__ float g_Oscr [(size_t)NBW * WLEN * DD];     // window outs; reused as mixed
__device__ float g_local[(size_t)BB * SS * DD];
__device__ float g_glob [(size_t)BB * SS * DD];
__device__ float g_xt   [(size_t)BB * DD * SS];
__device__ float g_bcast[(size_t)BB * SS * DD];
__device__ float g_gt   [(size_t)BB * 256 * DD];
__device__ float g_lg2  [(size_t)BB * SS * 256];
__device__ float g_Wc2  [(size_t)DD * 4096];
__device__ float g_xr   [(size_t)BB * SS * DD];        // tf32-rounded x
__device__ float g_Wmr  [(size_t)DD * 2 * DD];
__device__ float g_Wor  [(size_t)DD * DD];

__device__ __forceinline__ float rtf32(float v) {
    unsigned u;
    asm("cvt.rna.tf32.f32 %0, %1;" : "=r"(u) : "f"(v));
    return __uint_as_float(u);
}

struct GP {
    const float* A;
    const float* A2;    // second A matrix for K-concat (nullptr if unused)
    const float* B;
    float* C;
    int lda, ldb, ldc;
    long sA, sB, sC;
    int K, kSplit;
    float alpha;
    int beta, winA, winB, causal, klimit, roundOut;
};

__device__ __forceinline__ long window_off(int z) {
    return (long)(z / NWIN) * ((long)SS * DD) + (long)(z % NWIN) * (1024L * DD);
}

__device__ __forceinline__ void cp16(void* smem, const void* g) {
    uint32_t s = (uint32_t)__cvta_generic_to_shared(smem);
    asm volatile("cp.async.ca.shared.global [%0], [%1], 16;\n" :: "r"(s), "l"(g));
}
__device__ __forceinline__ void cp_commit() { asm volatile("cp.async.commit_group;\n"); }
template<int N> __device__ __forceinline__ void cp_wait() { asm volatile("cp.async.wait_group %0;\n" :: "n"(N)); }

// TB=1: C = A*B^T ; TB=0: C = A*B. Operands pre-rounded to tf32.
// 128 threads, 4 warps, each warp computes a 64x64 sub-tile of the 128x128 CTA tile.
template<int TB>
__global__ void __launch_bounds__(128) gemm_tf32(GP p) {
    constexpr int BM = 128, BN = 128, BK = 16, ST = 4;
    constexpr int AKP = 20;
    constexpr int BLD = TB ? 20 : 132;
    constexpr int BROWS = TB ? 128 : 16;
    constexpr int ASTG = BM * AKP;
    constexpr int BSTG = BROWS * BLD;

    int i0 = blockIdx.y * BM;
    int j0 = blockIdx.x * BN;
    if (p.causal && j0 > i0) return;
    int z = blockIdx.z;
    const float* A  = p.A + (p.winA ? window_off(z) : z * p.sA);
    const float* Bm = p.B + (p.winB ? window_off(z) : z * p.sB);
    float* C = p.C + z * p.sC;
    int K  = p.klimit ? min(p.K, i0 + BM) : p.K;
    int KT = K / BK;

    extern __shared__ float smem_dyn[];
    float* Asm = smem_dyn;
    float* Bsm = smem_dyn + ST * ASTG;

    int tid = threadIdx.x;
    int ar = tid >> 2, ac = (tid & 3) << 2;      // A: 32 rows/pass, 4 passes
    int br, bcd;
    if (TB) { br = tid >> 2;  bcd = (tid & 3) << 2;  }
    else    { br = tid >> 5;  bcd = (tid & 31) << 2; }

    auto load_tile = [&](int kt, int sl) {
        long acol = (long)kt * BK;
        const float* Ag;
        if (p.A2 && acol >= p.kSplit)
            Ag = p.A2 + (long)(i0 + ar) * p.lda + (acol - p.kSplit) + ac;
        else
            Ag = A + (long)(i0 + ar) * p.lda + acol + ac;
        float* As = Asm + sl * ASTG;
        #pragma unroll
        for (int q = 0; q < 4; q++)
            cp16(&As[(ar + 32 * q) * AKP + ac], Ag + (long)(32 * q) * p.lda);
        float* Bs = Bsm + sl * BSTG;
        if (TB) {
            const float* Bg = Bm + (long)(j0 + br) * p.ldb + acol + bcd;
            #pragma unroll
            for (int q = 0; q < 4; q++)
                cp16(&Bs[(br + 32 * q) * BLD + bcd], Bg + (long)(32 * q) * p.ldb);
        } else {
            const float* Bg = Bm + (acol + br) * (long)p.ldb + j0 + bcd;
            #pragma unroll
            for (int q = 0; q < 4; q++)
                cp16(&Bs[(br + 4 * q) * BLD + bcd], Bg + (long)(4 * q) * p.ldb);
        }
    };

    #pragma unroll
    for (int s = 0; s < ST - 1; s++) {
        if (s < KT) load_tile(s, s);
        cp_commit();
    }

    int wid = tid >> 5;
    int wr  = (wid & 1) * 64;
    int wc  = (wid >> 1) * 64;

    wmma::fragment<wmma::accumulator, 16, 16, 8, float> acc[4][4];
    #pragma unroll
    for (int i = 0; i < 4; i++)
        #pragma unroll
        for (int j = 0; j < 4; j++) wmma::fill_fragment(acc[i][j], 0.0f);

    for (int kt = 0; kt < KT; kt++) {
        cp_wait<ST - 2>();
        __syncthreads();
        if (kt + ST - 1 < KT) load_tile(kt + ST - 1, (kt + ST - 1) & (ST - 1));
        cp_commit();

        int sl = kt & (ST - 1);
        const float* As = Asm + sl * ASTG;
        const float* Bs = Bsm + sl * BSTG;

        #pragma unroll
        for (int ks = 0; ks < 2; ks++) {
            wmma::fragment<wmma::matrix_a, 16, 16, 8, wmma::precision::tf32, wmma::row_major> af[4];
            #pragma unroll
            for (int i = 0; i < 4; i++)
                wmma::load_matrix_sync(af[i], &As[(wr + i * 16) * AKP + ks * 8], AKP);
            #pragma unroll
            for (int j = 0; j < 4; j++) {
                if (TB) {
                    wmma::fragment<wmma::matrix_b, 16, 16, 8, wmma::precision::tf32, wmma::col_major> bf;
                    wmma::load_matrix_sync(bf, &Bs[(wc + j * 16) * BLD + ks * 8], BLD);
                    #pragma unroll
                    for (int i = 0; i < 4; i++)
                        wmma::mma_sync(acc[i][j], af[i], bf, acc[i][j]);
                } else {
                    wmma::fragment<wmma::matrix_b, 16, 16, 8, wmma::precision::tf32, wmma::row_major> bf;
                    wmma::load_matrix_sync(bf, &Bs[(ks * 8) * BLD + wc + j * 16], BLD);
                    #pragma unroll
                    for (int i = 0; i < 4; i++)
                        wmma::mma_sync(acc[i][j], af[i], bf, acc[i][j]);
                }
            }
        }
    }

    #pragma unroll
    for (int i = 0; i < 4; i++)
        #pragma unroll
        for (int j = 0; j < 4; j++) {
            #pragma unroll
            for (int t = 0; t < acc[i][j].num_elements; t++) acc[i][j].x[t] *= p.alpha;
            float* cp = C + (long)(i0 + wr + i * 16) * p.ldc + j0 + wc + j * 16;
            if (p.beta) {
                wmma::fragment<wmma::accumulator, 16, 16, 8, float> cf;
                wmma::load_matrix_sync(cf, cp, p.ldc, wmma::mem_row_major);
                #pragma unroll
                for (int t = 0; t < acc[i][j].num_elements; t++) acc[i][j].x[t] += cf.x[t];
            }
            if (p.roundOut) {
                #pragma unroll
                for (int t = 0; t < acc[i][j].num_elements; t++) acc[i][j].x[t] = rtf32(acc[i][j].x[t]);
            }
            wmma::store_matrix_sync(cp, acc[i][j], p.ldc, wmma::mem_row_major);
        }
}

#define SMEM_TB1 ((4 * (128 * 20) + 4 * (128 * 20)) * 4)
#define SMEM_TB0 ((4 * (128 * 20) + 4 * (16 * 132)) * 4)

// ---------------- rounded copy ----------------
__global__ void round_copy(const float* __restrict__ in, float* __restrict__ out, long n) {
    long idx = (long)blockIdx.x * 256 + threadIdx.x;
    if (idx < n) out[idx] = rtf32(in[idx]);
}

// ---------------- transpose (z, R x C) -> (z, C x R) ----------------
__global__ void transpose_k(const float* __restrict__ in, float* __restrict__ out, int R, int C) {
    __shared__ float t[32][33];
    long bo = (long)blockIdx.z * R * C;
    int r0 = blockIdx.y * 32, c0 = blockIdx.x * 32;
    int tx = threadIdx.x, ty = threadIdx.y;
    #pragma unroll
    for (int k = 0; k < 32; k += 8)
        t[ty + k][tx] = in[bo + (long)(r0 + ty + k) * C + c0 + tx];
    __syncthreads();
    #pragma unroll
    for (int k = 0; k < 32; k += 8)
        out[bo + (long)(c0 + ty + k) * R + r0 + tx] = t[tx][ty + k];
}

// ---------------- broadcast ----------------
__global__ void __launch_bounds__(256) bcast_k(float* xt) {
    __shared__ float a[SS];
    float res[32], nv[32];
    float* g = xt + (long)blockIdx.x * SS;
    int tid = threadIdx.x;
    #pragma unroll
    for (int j = 0; j < 32; j++) { a[tid + 256 * j] = g[tid + 256 * j]; res[j] = 0.0f; }
    __syncthreads();
    for (int s = 1; s < SS; s <<= 1) {
        #pragma unroll
        for (int j = 0; j < 32; j++) {
            int i = tid + 256 * j;
            nv[j] = a[i] + 0.5f * (a[(i - s) & (SS - 1)] + a[(i + s) & (SS - 1)]);
        }
        __syncthreads();
        #pragma unroll
        for (int j = 0; j < 32; j++) { int i = tid + 256 * j; a[i] = nv[j]; res[j] += nv[j]; }
        __syncthreads();
    }
    const float inv = 1.0f / 14.0f;
    #pragma unroll
    for (int j = 0; j < 32; j++) g[tid + 256 * j] = res[j] * inv;
}

__global__ void wc_reorder(const float* __restrict__ Wc, float* __restrict__ Wc2) {
    long idx = (long)blockIdx.x * 256 + threadIdx.x;
    int o = (int)(idx >> 12);
    int rem = (int)(idx & 4095);
    int k = rem >> 10;
    int d = rem & 1023;
    Wc2[idx] = rtf32(Wc[(long)o * 4096 + d * 4 + k]);
}

__global__ void build_gt(const float* __restrict__ gm, const float* __restrict__ bc, float* __restrict__ gt) {
    long idx = (long)blockIdx.x * 256 + threadIdx.x;
    int d = (int)(idx & 1023);
    int row = (int)((idx >> 10) & 255);
    gt[idx] = (row < GG) ? bc[d] : rtf32(gm[(long)(row - GG) * DD + d]);
}

__device__ __forceinline__ float blk_max(float v, float* red) {
    int tid = threadIdx.x;
    #pragma unroll
    for (int o = 16; o; o >>= 1) v = fmaxf(v, __shfl_xor_sync(0xffffffffu, v, o));
    if ((tid & 31) == 0) red[tid >> 5] = v;
    __syncthreads();
    float m = red[0];
    #pragma unroll
    for (int i = 1; i < 8; i++) m = fmaxf(m, red[i]);
    return m;
}
__device__ __forceinline__ float blk_sum(float v, float* red) {
    int tid = threadIdx.x;
    #pragma unroll
    for (int o = 16; o; o >>= 1) v += __shfl_xor_sync(0xffffffffu, v, o);
    if ((tid & 31) == 0) red[tid >> 5] = v;
    __syncthreads();
    float s = 0.f;
    #pragma unroll
    for (int i = 0; i < 8; i++) s += red[i];
    return s;
}

__global__ void softmax256(float* __restrict__ L) {
    __shared__ float red[8];
    float* r = L + (long)blockIdx.x * 256;
    int tid = threadIdx.x;
    float v = r[tid];
    float m = blk_max(v, red);
    __syncthreads();
    float e = expf(v - m);
    float s = blk_sum(e, red);
    r[tid] = rtf32(e / s);
}

__global__ void softmax_causal(float* __restrict__ Sc) {
    __shared__ float red[8];
    int q = blockIdx.x, w = blockIdx.y;
    float* r = Sc + ((long)w * WLEN + q) * WLEN;
    int len = q + 1;
    int rb = ((q >> 7) + 1) << 7;
    int tid = threadIdx.x;
    float v[8];
    int cnt = 0;
    float m = -1e30f;
    for (int i = tid; i < len; i += 256) { v[cnt] = r[i]; m = fmaxf(m, v[cnt]); cnt++; }
    m = blk_max(m, red);
    __syncthreads();
    float s = 0.f;
    #pragma unroll
    for (int j = 0; j < 8; j++) if (j < cnt) { v[j] = expf(v[j] - m); s += v[j]; }
    s = blk_sum(s, red);
    float inv = 1.0f / s;
    cnt = 0;
    for (int i = tid; i < len; i += 256) r[i] = rtf32(v[cnt++] * inv);
    for (int i = len + tid; i < rb; i += 256) r[i] = 0.0f;
}

__global__ void combine_local(const float* __restrict__ Oscr, float* __restrict__ local) {
    long idx = (long)blockIdx.x * 256 + threadIdx.x;
    int d = (int)(idx & 1023);
    long pd = idx >> 10;
    int p = (int)(pd & (SS - 1));
    int b = (int)(pd >> 13);
    int nhi = p >> 10;
    int n1 = min(nhi, NWIN - 1);
    int n0 = max(nhi - 1, 0);
    float acc = 0.f, wsum = 0.f;
    for (int n = n0; n <= n1; n++) {
        int q = p - (n << 10);
        float tri = 0.5f + q * (1.0f / 2047.0f);
        acc  += Oscr[(((long)(b * NWIN + n)) * WLEN + q) * DD + d] * tri;
        wsum += tri;
    }
    local[idx] = rtf32(acc / (wsum + 1e-6f));
}

__global__ void sigmoid_mix(const float* __restrict__ mwl, const float* __restrict__ bm,
                            const float* __restrict__ local, const float* __restrict__ glob,
                            const float* __restrict__ bcast, float* __restrict__ mixed) {
    long idx = (long)blockIdx.x * 256 + threadIdx.x;
    int o = (int)(idx & 1023);
    float g = 1.0f / (1.0f + expf(-(mwl[idx] + bm[o])));
    mixed[idx] = rtf32(g * local[idx] + (1.0f - g) * glob[idx] + bcast[idx]);
}

__global__ void fill_bias(float* __restrict__ out, const float* __restrict__ bo) {
    long idx = (long)blockIdx.x * 256 + threadIdx.x;
    out[idx] = bo[idx & 1023];
}

extern "C" void kernel_launch(void* const* d_in, const int* in_sizes, int n_in,
                              void* d_out, int out_size) {
    const float* x  = (const float*)d_in[0];
    const float* gm = (const float*)d_in[1];
    const float* Wc = (const float*)d_in[2];
    const float* bc = (const float*)d_in[3];
    const float* Wm = (const float*)d_in[4];
    const float* bm = (const float*)d_in[5];
    const float* Wo = (const float*)d_in[6];
    const float* bo = (const float*)d_in[7];
    float* out = (float*)d_out;

    float *Sscr, *Oscr, *local, *glob, *xt, *bcast, *gt, *lg2, *Wc2, *xr, *Wmr, *Wor;
    cudaGetSymbolAddress((void**)&Sscr,  g_Sscr);
    cudaGetSymbolAddress((void**)&Oscr,  g_Oscr);
    cudaGetSymbolAddress((void**)&local, g_local);
    cudaGetSymbolAddress((void**)&glob,  g_glob);
    cudaGetSymbolAddress((void**)&xt,    g_xt);
    cudaGetSymbolAddress((void**)&bcast, g_bcast);
    cudaGetSymbolAddress((void**)&gt,    g_gt);
    cudaGetSymbolAddress((void**)&lg2,   g_lg2);
    cudaGetSymbolAddress((void**)&Wc2,   g_Wc2);
    cudaGetSymbolAddress((void**)&xr,    g_xr);
    cudaGetSymbolAddress((void**)&Wmr,   g_Wmr);
    cudaGetSymbolAddress((void**)&Wor,   g_Wor);

    cudaFuncSetAttribute(gemm_tf32<1>, cudaFuncAttributeMaxDynamicSharedMemorySize, SMEM_TB1);
    cudaFuncSetAttribute(gemm_tf32<0>, cudaFuncAttributeMaxDynamicSharedMemorySize, SMEM_TB0);

    const float isq = 1.0f / 32.0f;
    const long SD = (long)SS * DD;

    round_copy<<<(int)((SD * BB + 255) / 256), 256>>>(x, xr, SD * BB);
    round_copy<<<(2 * 1024 * 1024 + 255) / 256, 256>>>(Wm, Wmr, 2L * 1024 * 1024);
    round_copy<<<(1024 * 1024 + 255) / 256, 256>>>(Wo, Wor, 1024L * 1024);
    wc_reorder<<<16384, 256>>>(Wc, Wc2);
    build_gt<<<2048, 256>>>(gm, bc, gt);

    // comp = xr_view @ Wc2^T (+bc preload), rounded output
    {
        GP p{}; p.A = xr; p.B = Wc2; p.C = gt;
        p.lda = 4096; p.ldb = 4096; p.ldc = 1024;
        p.sA = SD; p.sC = 256L * 1024;
        p.K = 4096; p.alpha = 1.0f; p.beta = 1; p.roundOut = 1;
        gemm_tf32<1><<<dim3(8, 1, 2), 128, SMEM_TB1>>>(p);
    }
    // logits = xr @ gt^T / 32
    {
        GP p{}; p.A = xr; p.B = gt; p.C = lg2;
        p.lda = 1024; p.ldb = 1024; p.ldc = 256;
        p.sA = SD; p.sB = 256L * 1024; p.sC = (long)SS * 256;
        p.K = 1024; p.alpha = isq;
        gemm_tf32<1><<<dim3(2, 64, 2), 128, SMEM_TB1>>>(p);
    }
    softmax256<<<BB * SS, 256>>>(lg2);
    // glob = attn @ gt, rounded output
    {
        GP p{}; p.A = lg2; p.B = gt; p.C = glob;
        p.lda = 256; p.ldb = 1024; p.ldc = 1024;
        p.sA = (long)SS * 256; p.sB = 256L * 1024; p.sC = SD;
        p.K = 256; p.alpha = 1.0f; p.roundOut = 1;
        gemm_tf32<0><<<dim3(8, 64, 2), 128, SMEM_TB0>>>(p);
    }
    // window scores = w @ w^T / 32 (causal skip)
    {
        GP p{}; p.A = xr; p.B = xr; p.C = Sscr;
        p.lda = 1024; p.ldb = 1024; p.ldc = WLEN;
        p.sC = (long)WLEN * WLEN;
        p.K = 1024; p.alpha = isq;
        p.winA = 1; p.winB = 1; p.causal = 1;
        gemm_tf32<1><<<dim3(16, 16, NBW), 128, SMEM_TB1>>>(p);
    }
    softmax_causal<<<dim3(WLEN, NBW), 256>>>(Sscr);
    // out_w = P @ w (K limited per row block)
    {
        GP p{}; p.A = Sscr; p.B = xr; p.C = Oscr;
        p.lda = WLEN; p.ldb = 1024; p.ldc = 1024;
        p.sA = (long)WLEN * WLEN; p.sC = (long)WLEN * DD;
        p.K = WLEN; p.alpha = 1.0f;
        p.winB = 1; p.klimit = 1;
        gemm_tf32<0><<<dim3(8, 16, NBW), 128, SMEM_TB0>>>(p);
    }
    combine_local<<<65536, 256>>>(Oscr, local);

    // broadcast path (exact fp32, unrounded x)
    transpose_k<<<dim3(32, 256, 2), dim3(32, 8)>>>(x, xt, SS, DD);
    bcast_k<<<BB * DD, 256>>>(xt);
    transpose_k<<<dim3(256, 32, 2), dim3(32, 8)>>>(xt, bcast, DD, SS);

    // mw logits = [local|glob] @ Wmr^T (dual-A, K=2048)
    {
        GP p{}; p.A = local; p.A2 = glob; p.B = Wmr; p.C = Sscr;
        p.lda = 1024; p.ldb = 2048; p.ldc = 1024;
        p.K = 2048; p.kSplit = 1024; p.alpha = 1.0f;
        gemm_tf32<1><<<dim3(8, 128, 1), 128, SMEM_TB1>>>(p);
    }
    sigmoid_mix<<<65536, 256>>>(Sscr, bm, local, glob, bcast, Oscr);

    // out = mixed @ Wor^T + bo
    fill_bias<<<65536, 256>>>(out, bo);
    {
        GP p{}; p.A = Oscr; p.B = Wor; p.C = out;
        p.lda = 1024; p.ldb = 1024; p.ldc = 1024;
        p.K = 1024; p.alpha = 1.0f; p.beta = 1;
        gemm_tf32<1><<<dim3(8, 128, 1), 128, SMEM_TB1>>>(p);
    }
}